// round 1
// baseline (speedup 1.0000x reference)
#include <cuda_runtime.h>
#include <math.h>

// ---------------- problem constants ----------------
#define DN     160
#define MS     64
#define MV     32
#define NGROUP 16
#define FCIN   128
#define MAXN   10000
#define EPB    8

#define INV8        0.125f
#define INV16       0.0625f
#define INV_SQRT32  0.17677669529663687f
#define INV_SQRT128 0.08838834764831845f
#define INV_SQRT3   0.5773502691896258f
#define INV_FAN     0.05892556509887896f   /* 1/sqrt(3*MS+3*MV) */
#define LN_EPS      1e-5f

// ---------------- device scratch (no allocs allowed) ----------------
__device__ float g_s  [MAXN * MS];      // lp-transformed scalars
__device__ float g_v  [MAXN * MV * 3];  // lp-transformed vectors
__device__ float g_scs[MAXN * MS];      // self-connection scalars
__device__ float g_scv[MAXN * MV * 3];  // self-connection vectors
__device__ float g_ns [MAXN * MS];      // edge-aggregated scalars
__device__ float g_nv [MAXN * MV * 3];  // edge-aggregated vectors
__device__ float g_ps [MAXN * MS];      // pre-norm scalars
__device__ float g_pv [MAXN * MV * 3];  // pre-norm vectors
__device__ float g_stats[NGROUP * 4];   // sum(mean_s), sum(mean_s^2), sum(mean_v^2), count
__device__ float g_norm [NGROUP * 3];   // mu, inv_std_s, inv_std_v

__device__ __forceinline__ float silu_f(float x) { return x / (1.f + __expf(-x)); }
__device__ __forceinline__ float sigm_f(float x) { return 1.f / (1.f + __expf(-x)); }

// ---------------- zero scratch ----------------
__global__ void k_zero(int N) {
    int tot = N * DN + NGROUP * 4;
    for (int i = blockIdx.x * blockDim.x + threadIdx.x; i < tot; i += gridDim.x * blockDim.x) {
        if (i < N * MS)      g_ns[i] = 0.f;
        else if (i < N * DN) g_nv[i - N * MS] = 0.f;
        else                 g_stats[i - N * DN] = 0.f;
    }
}

// ---------------- node pre: lp + self-connection ----------------
__global__ __launch_bounds__(96) void k_node_pre(
    const float* __restrict__ nf, const float* __restrict__ onehot,
    const float* __restrict__ lpWs, const float* __restrict__ lpbs,
    const float* __restrict__ lpWv,
    const float* __restrict__ scWs, const float* __restrict__ scWv)
{
    const int n = blockIdx.x;
    const int t = threadIdx.x;
    __shared__ float ss[MS];
    __shared__ float sv[MV * 3];
    __shared__ int ssp;

    if (t < MS) ss[t] = nf[n * DN + t];
    sv[t] = nf[n * DN + MS + t];              // t in [0,96)
    if (t == 0) {
        int sp = 0; float best = onehot[n * 4];
        #pragma unroll
        for (int k = 1; k < 4; k++) { float v = onehot[n * 4 + k]; if (v > best) { best = v; sp = k; } }
        ssp = sp;
    }
    __syncthreads();
    const int sp = ssp;

    if (t < MS) {
        float a = 0.f, b = 0.f;
        #pragma unroll 8
        for (int u = 0; u < MS; u++) {
            float x = ss[u];
            a += x * lpWs[u * MS + t];
            b += x * scWs[(u * 4 + sp) * MS + t];
        }
        g_s  [n * MS + t] = a * INV8 + lpbs[t];
        g_scs[n * MS + t] = b * INV16;
    }
    {
        const int w = t / 3, i = t - w * 3;
        float a = 0.f, b = 0.f;
        #pragma unroll 8
        for (int u = 0; u < MV; u++) {
            float x = sv[u * 3 + i];
            a += x * lpWv[u * MV + w];
            b += x * scWv[(u * 4 + sp) * MV + w];
        }
        g_v  [n * 96 + w * 3 + i] = a * INV_SQRT32;
        g_scv[n * 96 + w * 3 + i] = b * INV_SQRT128;
    }
}

// ---------------- edge kernel: 8 edges / 128-thread block ----------------
__global__ __launch_bounds__(128) void k_edge(
    const float* __restrict__ edge_sh, const float* __restrict__ edge_fea,
    const float* __restrict__ ele,     const int*   __restrict__ edge_index,
    const float* __restrict__ Wss0, const float* __restrict__ Wvv0,
    const float* __restrict__ Wssg, const float* __restrict__ Wvvg,
    const float* __restrict__ Wsv1, const float* __restrict__ Wvs1,
    const float* __restrict__ fW1, const float* __restrict__ fb1,
    const float* __restrict__ fW2, const float* __restrict__ fb2,
    const float* __restrict__ fW3, const float* __restrict__ fb3,
    int E)
{
    __shared__ __align__(16) float sS1 [EPB][192];
    __shared__ __align__(16) float sV1 [EPB][3][96];
    __shared__ __align__(16) float sDD [EPB][96];
    __shared__ __align__(16) float sELE[EPB][FCIN];
    __shared__ __align__(16) float sH1 [EPB][64];
    __shared__ __align__(16) float sH2 [EPB][64];
    __shared__ __align__(16) float sWfc[EPB][96];
    __shared__ float sSG[EPB][MV];
    __shared__ float sT1[EPB][MV];
    __shared__ float sSH[EPB][4];
    __shared__ int   sI[EPB], sJ[EPB], sOK[EPB];

    const int t  = threadIdx.x;
    const int e0 = blockIdx.x * EPB;

    if (t < EPB) {
        int eg = e0 + t;
        int ok = (eg < E);
        sOK[t] = ok;
        sI[t]  = ok ? edge_index[eg]     : 0;
        sJ[t]  = ok ? edge_index[E + eg] : 0;
    }
    __syncthreads();

    // ---- stage inputs ----
    #pragma unroll
    for (int e = 0; e < EPB; e++) {
        const int eg = e0 + e;
        const bool ok = (sOK[e] != 0);
        const int ni = sI[e], nj = sJ[e];
        if (t < 64) {
            sS1[e][t]       = ok ? g_s[ni * MS + t] : 0.f;
            sS1[e][128 + t] = ok ? edge_fea[eg * DN + t] : 0.f;
        } else {
            sS1[e][t] = ok ? g_s[nj * MS + (t - 64)] : 0.f;
        }
        if (t < 96) {
            const int u = t / 3, ii = t - u * 3;
            sV1[e][ii][u]      = ok ? g_v[ni * 96 + t] : 0.f;
            sV1[e][ii][32 + u] = ok ? g_v[nj * 96 + t] : 0.f;
            sV1[e][ii][64 + u] = ok ? edge_fea[eg * DN + MS + t] : 0.f;
        }
        sELE[e][t] = ok ? ele[eg * FCIN + t] : 0.f;
        if (t < 4) sSH[e][t] = ok ? edge_sh[eg * 4 + t] : 0.f;
    }
    __syncthreads();

    // ---- dd = <v1, sh1>/sqrt(3) ----
    for (int id = t; id < EPB * 96; id += 128) {
        const int e = id / 96, u = id - e * 96;
        sDD[e][u] = (sV1[e][0][u] * sSH[e][1] + sV1[e][1][u] * sSH[e][2] +
                     sV1[e][2][u] * sSH[e][3]) * INV_SQRT3;
    }

    // ---- fc1: 128 threads, each (w, half) does 4 edges ----
    {
        const int w = t & 63, half = t >> 6;
        float acc[4] = {0.f, 0.f, 0.f, 0.f};
        #pragma unroll 4
        for (int u4 = 0; u4 < FCIN / 4; u4++) {
            const float w0 = fW1[(u4 * 4 + 0) * 64 + w];
            const float w1 = fW1[(u4 * 4 + 1) * 64 + w];
            const float w2 = fW1[(u4 * 4 + 2) * 64 + w];
            const float w3 = fW1[(u4 * 4 + 3) * 64 + w];
            #pragma unroll
            for (int k = 0; k < 4; k++) {
                float4 x = reinterpret_cast<const float4*>(sELE[half + 2 * k])[u4];
                acc[k] += x.x * w0 + x.y * w1 + x.z * w2 + x.w * w3;
            }
        }
        const float b = fb1[w];
        #pragma unroll
        for (int k = 0; k < 4; k++) sH1[half + 2 * k][w] = silu_f(acc[k] + b);
    }
    __syncthreads();

    // ---- fc2 ----
    {
        const int w = t & 63, half = t >> 6;
        float acc[4] = {0.f, 0.f, 0.f, 0.f};
        #pragma unroll 4
        for (int u4 = 0; u4 < 16; u4++) {
            const float w0 = fW2[(u4 * 4 + 0) * 64 + w];
            const float w1 = fW2[(u4 * 4 + 1) * 64 + w];
            const float w2 = fW2[(u4 * 4 + 2) * 64 + w];
            const float w3 = fW2[(u4 * 4 + 3) * 64 + w];
            #pragma unroll
            for (int k = 0; k < 4; k++) {
                float4 x = reinterpret_cast<const float4*>(sH1[half + 2 * k])[u4];
                acc[k] += x.x * w0 + x.y * w1 + x.z * w2 + x.w * w3;
            }
        }
        const float b = fb2[w];
        #pragma unroll
        for (int k = 0; k < 4; k++) sH2[half + 2 * k][w] = silu_f(acc[k] + b);
    }
    __syncthreads();

    // ---- fc3 -> per-edge filter weights ----
    if (t < 96) {
        const int w = t;
        float acc[EPB];
        #pragma unroll
        for (int e = 0; e < EPB; e++) acc[e] = 0.f;
        #pragma unroll 4
        for (int u4 = 0; u4 < 16; u4++) {
            const float w0 = fW3[(u4 * 4 + 0) * 96 + w];
            const float w1 = fW3[(u4 * 4 + 1) * 96 + w];
            const float w2 = fW3[(u4 * 4 + 2) * 96 + w];
            const float w3 = fW3[(u4 * 4 + 3) * 96 + w];
            #pragma unroll
            for (int e = 0; e < EPB; e++) {
                float4 x = reinterpret_cast<const float4*>(sH2[e])[u4];
                acc[e] += x.x * w0 + x.y * w1 + x.z * w2 + x.w * w3;
            }
        }
        const float b = fb3[w];
        #pragma unroll
        for (int e = 0; e < EPB; e++) sWfc[e][w] = acc[e] + b;
    }
    __syncthreads();

    // ---- zs (t<64) | zg (64<=t<96) | t1 (96<=t<128) ----
    if (t < 64) {
        const int w = t;
        float accA[EPB], accB[EPB];
        #pragma unroll
        for (int e = 0; e < EPB; e++) { accA[e] = 0.f; accB[e] = 0.f; }
        #pragma unroll 2
        for (int u4 = 0; u4 < 48; u4++) {
            const float w0 = Wss0[(u4 * 4 + 0) * 64 + w];
            const float w1 = Wss0[(u4 * 4 + 1) * 64 + w];
            const float w2 = Wss0[(u4 * 4 + 2) * 64 + w];
            const float w3 = Wss0[(u4 * 4 + 3) * 64 + w];
            #pragma unroll
            for (int e = 0; e < EPB; e++) {
                float4 x = reinterpret_cast<const float4*>(sS1[e])[u4];
                accA[e] += x.x * w0 + x.y * w1 + x.z * w2 + x.w * w3;
            }
        }
        #pragma unroll 2
        for (int u4 = 0; u4 < 24; u4++) {
            const float w0 = Wvv0[(u4 * 4 + 0) * 64 + w];
            const float w1 = Wvv0[(u4 * 4 + 1) * 64 + w];
            const float w2 = Wvv0[(u4 * 4 + 2) * 64 + w];
            const float w3 = Wvv0[(u4 * 4 + 3) * 64 + w];
            #pragma unroll
            for (int e = 0; e < EPB; e++) {
                float4 x = reinterpret_cast<const float4*>(sDD[e])[u4];
                accB[e] += x.x * w0 + x.y * w1 + x.z * w2 + x.w * w3;
            }
        }
        #pragma unroll
        for (int e = 0; e < EPB; e++) {
            if (sOK[e]) {
                float z = (accA[e] * sSH[e][0] + accB[e]) * INV_FAN;
                float val = silu_f(z) * sWfc[e][w];
                atomicAdd(&g_ns[sI[e] * MS + w], val);
            }
        }
    } else if (t < 96) {
        const int w = t - 64;
        float accA[EPB], accB[EPB];
        #pragma unroll
        for (int e = 0; e < EPB; e++) { accA[e] = 0.f; accB[e] = 0.f; }
        #pragma unroll 2
        for (int u4 = 0; u4 < 48; u4++) {
            const float w0 = Wssg[(u4 * 4 + 0) * 32 + w];
            const float w1 = Wssg[(u4 * 4 + 1) * 32 + w];
            const float w2 = Wssg[(u4 * 4 + 2) * 32 + w];
            const float w3 = Wssg[(u4 * 4 + 3) * 32 + w];
            #pragma unroll
            for (int e = 0; e < EPB; e++) {
                float4 x = reinterpret_cast<const float4*>(sS1[e])[u4];
                accA[e] += x.x * w0 + x.y * w1 + x.z * w2 + x.w * w3;
            }
        }
        #pragma unroll 2
        for (int u4 = 0; u4 < 24; u4++) {
            const float w0 = Wvvg[(u4 * 4 + 0) * 32 + w];
            const float w1 = Wvvg[(u4 * 4 + 1) * 32 + w];
            const float w2 = Wvvg[(u4 * 4 + 2) * 32 + w];
            const float w3 = Wvvg[(u4 * 4 + 3) * 32 + w];
            #pragma unroll
            for (int e = 0; e < EPB; e++) {
                float4 x = reinterpret_cast<const float4*>(sDD[e])[u4];
                accB[e] += x.x * w0 + x.y * w1 + x.z * w2 + x.w * w3;
            }
        }
        #pragma unroll
        for (int e = 0; e < EPB; e++) {
            float zg = (accA[e] * sSH[e][0] + accB[e]) * INV_FAN;
            sSG[e][w] = sigm_f(zg);
        }
    } else {
        const int w = t - 96;
        float accA[EPB];
        #pragma unroll
        for (int e = 0; e < EPB; e++) accA[e] = 0.f;
        #pragma unroll 2
        for (int u4 = 0; u4 < 48; u4++) {
            const float w0 = Wsv1[(u4 * 4 + 0) * 32 + w];
            const float w1 = Wsv1[(u4 * 4 + 1) * 32 + w];
            const float w2 = Wsv1[(u4 * 4 + 2) * 32 + w];
            const float w3 = Wsv1[(u4 * 4 + 3) * 32 + w];
            #pragma unroll
            for (int e = 0; e < EPB; e++) {
                float4 x = reinterpret_cast<const float4*>(sS1[e])[u4];
                accA[e] += x.x * w0 + x.y * w1 + x.z * w2 + x.w * w3;
            }
        }
        #pragma unroll
        for (int e = 0; e < EPB; e++) sT1[e][w] = accA[e];
    }
    __syncthreads();

    // ---- zv: t2 + combine + scatter ----
    if (t < 96) {
        const int w = t & 31, ii = t >> 5;
        float acc[EPB];
        #pragma unroll
        for (int e = 0; e < EPB; e++) acc[e] = 0.f;
        #pragma unroll 2
        for (int u4 = 0; u4 < 24; u4++) {
            const float w0 = Wvs1[(u4 * 4 + 0) * 32 + w];
            const float w1 = Wvs1[(u4 * 4 + 1) * 32 + w];
            const float w2 = Wvs1[(u4 * 4 + 2) * 32 + w];
            const float w3 = Wvs1[(u4 * 4 + 3) * 32 + w];
            #pragma unroll
            for (int e = 0; e < EPB; e++) {
                float4 x = reinterpret_cast<const float4*>(&sV1[e][ii][0])[u4];
                acc[e] += x.x * w0 + x.y * w1 + x.z * w2 + x.w * w3;
            }
        }
        #pragma unroll
        for (int e = 0; e < EPB; e++) {
            if (sOK[e]) {
                float zv = (sT1[e][w] * sSH[e][1 + ii] + acc[e] * sSH[e][0]) * INV_FAN;
                zv *= sSG[e][w] * sWfc[e][64 + w];
                atomicAdd(&g_nv[sI[e] * 96 + w * 3 + ii], zv);
            }
        }
    }
}

// ---------------- node post: pp transforms + sc add + group stat partials ----------------
__global__ __launch_bounds__(96) void k_node_post(
    const float* __restrict__ ppWs, const float* __restrict__ ppbs,
    const float* __restrict__ ppWv, const int* __restrict__ batch)
{
    const int n = blockIdx.x;
    const int t = threadIdx.x;
    __shared__ float sns[MS];
    __shared__ float snv[MV * 3];
    __shared__ float red[3];

    if (t < MS) sns[t] = g_ns[n * MS + t];
    snv[t] = g_nv[n * 96 + t];
    if (t < 3) red[t] = 0.f;
    __syncthreads();

    float ps = 0.f, ps2 = 0.f, pv2 = 0.f;
    if (t < MS) {
        float a = 0.f;
        #pragma unroll 8
        for (int u = 0; u < MS; u++) a += sns[u] * ppWs[u * MS + t];
        float val = a * INV8 + ppbs[t] + g_scs[n * MS + t];
        g_ps[n * MS + t] = val;
        ps = val; ps2 = val * val;
    }
    {
        const int w = t / 3, i = t - w * 3;
        float a = 0.f;
        #pragma unroll 8
        for (int u = 0; u < MV; u++) a += snv[u * 3 + i] * ppWv[u * MV + w];
        float val = a * INV_SQRT32 + g_scv[n * 96 + t];
        g_pv[n * 96 + t] = val;
        pv2 = val * val;
    }
    atomicAdd(&red[0], ps);
    atomicAdd(&red[1], ps2);
    atomicAdd(&red[2], pv2);
    __syncthreads();
    if (t == 0) {
        const int g = batch[n];
        atomicAdd(&g_stats[g * 4 + 0], red[0] * (1.f / 64.f));
        atomicAdd(&g_stats[g * 4 + 1], red[1] * (1.f / 64.f));
        atomicAdd(&g_stats[g * 4 + 2], red[2] * (1.f / 96.f));
        atomicAdd(&g_stats[g * 4 + 3], 1.f);
    }
}

// ---------------- group stats finalize ----------------
__global__ void k_stats() {
    const int g = threadIdx.x;
    if (g < NGROUP) {
        float cnt = fmaxf(g_stats[g * 4 + 3], 1.f);
        float mu  = g_stats[g * 4 + 0] / cnt;
        float vs  = fmaxf(g_stats[g * 4 + 1] / cnt - mu * mu, 0.f);
        float vv  = g_stats[g * 4 + 2] / cnt;
        g_norm[g * 3 + 0] = mu;
        g_norm[g * 3 + 1] = rsqrtf(vs + LN_EPS);
        g_norm[g * 3 + 2] = rsqrtf(vv + LN_EPS);
    }
}

// ---------------- finalize output ----------------
__global__ void k_finalize(
    const float* __restrict__ nf, const int* __restrict__ batch,
    const float* __restrict__ lnws, const float* __restrict__ lnbs,
    const float* __restrict__ lnwv, float* __restrict__ out, int N)
{
    const int total = N * DN;
    for (int idx = blockIdx.x * blockDim.x + threadIdx.x; idx < total;
         idx += gridDim.x * blockDim.x) {
        const int n = idx / DN;
        const int c = idx - n * DN;
        const int g = batch[n];
        float o;
        if (c < MS) {
            float mu = g_norm[g * 3 + 0], is = g_norm[g * 3 + 1];
            o = nf[idx] + (g_ps[n * MS + c] - mu) * is * lnws[c] + lnbs[c];
        } else {
            const int u3 = c - MS;
            float iv = g_norm[g * 3 + 2];
            o = nf[idx] + g_pv[n * 96 + u3] * iv * lnwv[u3 / 3];
        }
        out[idx] = o;
    }
}

// ---------------- launch ----------------
extern "C" void kernel_launch(void* const* d_in, const int* in_sizes, int n_in,
                              void* d_out, int out_size)
{
    const float* node_fea = (const float*)d_in[0];
    const float* onehot   = (const float*)d_in[1];
    const float* edge_sh  = (const float*)d_in[2];
    const float* edge_fea = (const float*)d_in[3];
    const float* ele      = (const float*)d_in[4];
    const int*   edge_idx = (const int*)  d_in[5];
    const int*   batch    = (const int*)  d_in[6];
    const float* lpWs = (const float*)d_in[7];
    const float* lpbs = (const float*)d_in[8];
    const float* lpWv = (const float*)d_in[9];
    const float* ppWs = (const float*)d_in[10];
    const float* ppbs = (const float*)d_in[11];
    const float* ppWv = (const float*)d_in[12];
    const float* scWs = (const float*)d_in[13];
    const float* scWv = (const float*)d_in[14];
    const float* Wss0 = (const float*)d_in[15];
    const float* Wvv0 = (const float*)d_in[16];
    const float* Wssg = (const float*)d_in[17];
    const float* Wvvg = (const float*)d_in[18];
    const float* Wsv1 = (const float*)d_in[19];
    const float* Wvs1 = (const float*)d_in[20];
    const float* fW1  = (const float*)d_in[21];
    const float* fb1  = (const float*)d_in[22];
    const float* fW2  = (const float*)d_in[23];
    const float* fb2  = (const float*)d_in[24];
    const float* fW3  = (const float*)d_in[25];
    const float* fb3  = (const float*)d_in[26];
    const float* lnws = (const float*)d_in[27];
    const float* lnbs = (const float*)d_in[28];
    const float* lnwv = (const float*)d_in[29];
    float* out = (float*)d_out;

    const int N = in_sizes[0] / DN;
    const int E = in_sizes[2] / 4;

    const int zt = N * DN + NGROUP * 4;
    k_zero<<<(zt + 255) / 256, 256>>>(N);
    k_node_pre<<<N, 96>>>(node_fea, onehot, lpWs, lpbs, lpWv, scWs, scWv);
    k_edge<<<(E + EPB - 1) / EPB, 128>>>(edge_sh, edge_fea, ele, edge_idx,
                                         Wss0, Wvv0, Wssg, Wvvg, Wsv1, Wvs1,
                                         fW1, fb1, fW2, fb2, fW3, fb3, E);
    k_node_post<<<N, 96>>>(ppWs, ppbs, ppWv, batch);
    k_stats<<<1, 32>>>();
    k_finalize<<<(N * DN + 255) / 256, 256>>>(node_fea, batch, lnws, lnbs, lnwv, out, N);
}